// round 8
// baseline (speedup 1.0000x reference)
#include <cuda_runtime.h>
#include <cuda_bf16.h>
#include <cstdint>

#define BQ 4096
#define ZD 512
#define HD 384
#define KD2 768
#define KC 32

// ---------------- device state ----------------
__device__ float g_z[2][(size_t)BQ * ZD];
__device__ float g_h[2][(size_t)BQ * HD];
__device__ __nv_bfloat16 g_zh[2][(size_t)BQ * ZD];
__device__ __nv_bfloat16 g_zl[2][(size_t)BQ * ZD];
__device__ __nv_bfloat16 g_hh[2][(size_t)BQ * HD];
__device__ __nv_bfloat16 g_hl[2][(size_t)BQ * HD];
__device__ __nv_bfloat16 g_ah[(size_t)BQ * HD];
__device__ __nv_bfloat16 g_al[(size_t)BQ * HD];
__device__ __nv_bfloat16 g_w1h[(size_t)HD * ZD], g_w1l[(size_t)HD * ZD];
__device__ __nv_bfloat16 g_w2h[(size_t)ZD * KD2], g_w2l[(size_t)ZD * KD2];
__device__ __nv_bfloat16 g_w3h[(size_t)HD * KD2], g_w3l[(size_t)HD * KD2];

// ---------------- helpers ----------------
__device__ __forceinline__ uint32_t smem_to_u32(const void* p) {
    uint32_t a;
    asm("{ .reg .u64 t; cvta.to.shared.u64 t, %1; cvt.u32.u64 %0, t; }" : "=r"(a) : "l"(p));
    return a;
}
__device__ __forceinline__ float lrelu(float x) { return x > 0.f ? x : 0.01f * x; }
__device__ __forceinline__ uint32_t pack_bf2(float a, float b) {
    uint32_t r;
    asm("cvt.rn.bf16x2.f32 %0, %1, %2;" : "=r"(r) : "f"(b), "f"(a));
    return r;
}
__device__ __forceinline__ void split_bf(float v, __nv_bfloat16& h, __nv_bfloat16& l) {
    h = __float2bfloat16(v);
    l = __float2bfloat16(v - __bfloat162float(h));
}
__device__ __forceinline__ uint32_t swz(uint32_t row, uint32_t c) {
    return row * 64u + ((c ^ ((row >> 1) & 3u)) << 4);
}

#define CP_ASYNC16(dst, src) \
    asm volatile("cp.async.cg.shared.global [%0], [%1], 16;" \
                 :: "r"(dst), "l"((unsigned long long)__cvta_generic_to_global(src)) : "memory")
#define CP_COMMIT() asm volatile("cp.async.commit_group;" ::: "memory")

#define LDSM_X4(r0, r1, r2, r3, addr) \
    asm volatile("ldmatrix.sync.aligned.m8n8.x4.shared.b16 {%0,%1,%2,%3}, [%4];" \
                 : "=r"(r0), "=r"(r1), "=r"(r2), "=r"(r3) : "r"(addr))

#define MMA_BF16(c, a, b) \
    asm volatile("mma.sync.aligned.m16n8k16.row.col.f32.bf16.bf16.f32 " \
                 "{%0,%1,%2,%3}, {%4,%5,%6,%7}, {%8,%9}, {%0,%1,%2,%3};" \
                 : "+f"((c)[0]), "+f"((c)[1]), "+f"((c)[2]), "+f"((c)[3]) \
                 : "r"((a)[0]), "r"((a)[1]), "r"((a)[2]), "r"((a)[3]), \
                   "r"((b)[0]), "r"((b)[1]))

// ---------------- prep / init ----------------
__global__ void prep_weights(const float* __restrict__ W1, const float* __restrict__ W2,
                             const float* __restrict__ W3)
{
    int i = blockIdx.x * 256 + threadIdx.x;
    const int s1 = HD * ZD, s2 = ZD * KD2, s3 = HD * KD2;
    if (i < s1) { __nv_bfloat16 h, l; split_bf(W1[i], h, l); g_w1h[i] = h; g_w1l[i] = l; }
    else if (i < s1 + s2) { int j = i - s1; __nv_bfloat16 h, l; split_bf(W2[j], h, l); g_w2h[j] = h; g_w2l[j] = l; }
    else if (i < s1 + s2 + s3) { int j = i - s1 - s2; __nv_bfloat16 h, l; split_bf(W3[j], h, l); g_w3h[j] = h; g_w3l[j] = l; }
}

__global__ void init_kernel(const float* __restrict__ z, const float* __restrict__ hin,
                            float* __restrict__ out, int T)
{
    int idx = blockIdx.x * blockDim.x + threadIdx.x;
    if (idx < BQ * ZD) {
        float v = z[idx];
        g_z[0][idx] = v;
        __nv_bfloat16 h, l; split_bf(v, h, l);
        g_zh[0][idx] = h; g_zl[0][idx] = l;
        int m = idx >> 9, n = idx & (ZD - 1);
        out[((size_t)m * T) * ZD + n] = 0.f;
    }
    if (idx < BQ * HD) {
        float v = hin[idx];
        g_h[0][idx] = v;
        __nv_bfloat16 h, l; split_bf(v, h, l);
        g_hh[0][idx] = h; g_hl[0][idx] = l;
    }
}

// ---------------- tensor-core GEMM (mma.sync bf16 split) ----------------
// Tile TM(M) x 128(N), 128 threads (4 warps, 2x2), warp tile (TM/2)x64,
// XOR-swizzled smem, 3-stage cp.async pipeline, ONE barrier per chunk.
template <int TM>
__global__ __launch_bounds__(128, (TM == 128) ? 2 : 3)
void rec_gemm(int kind, int parity, int t, float r,
              const float* __restrict__ b1, const float* __restrict__ b2,
              const float* __restrict__ b3, const float* __restrict__ z0,
              float* __restrict__ out, int T)
{
    constexpr int MF = TM / 32;                 // m16 frags per warp
    constexpr int A_TILE_B = TM * 64;
    constexpr int B_TILE_B = 128 * 64;
    constexpr int OFF_AH = 0;
    constexpr int OFF_AL = A_TILE_B;
    constexpr int OFF_BH = 2 * A_TILE_B;
    constexpr int OFF_BL = 2 * A_TILE_B + B_TILE_B;
    constexpr int STAGE_B = 2 * A_TILE_B + 2 * B_TILE_B;
    constexpr int NA = TM * 4;
    constexpr int NVEC = (2 * NA + 1024) / 128;

    extern __shared__ char smem[];
    const uint32_t sb = smem_to_u32(smem);
    const int tid = threadIdx.x;
    const int wid = tid >> 5, lane = tid & 31;
    const int wm = (wid >> 1) * (TM / 2);
    const int wn = (wid & 1) * 64;
    const int n0 = blockIdx.x * 128;
    const int row0 = blockIdx.y * TM;
    const bool is_z = (n0 < ZD);
    const int NCH = kind ? (KD2 / KC) : (ZD / KC);

    const __nv_bfloat16 *Bh, *Bl;
    int bs;
    if (kind == 0)  { Bh = g_w1h + (size_t)n0 * ZD;         Bl = g_w1l + (size_t)n0 * ZD;         bs = ZD; }
    else if (is_z)  { Bh = g_w2h + (size_t)n0 * KD2;        Bl = g_w2l + (size_t)n0 * KD2;        bs = KD2; }
    else            { Bh = g_w3h + (size_t)(n0 - ZD) * KD2; Bl = g_w3l + (size_t)(n0 - ZD) * KD2; bs = KD2; }

    float acc[MF][8][4];
#pragma unroll
    for (int i = 0; i < MF; i++)
#pragma unroll
        for (int j = 0; j < 8; j++)
#pragma unroll
            for (int k = 0; k < 4; k++) acc[i][j][k] = 0.f;

    const int a_row = wm + (lane & 7) + ((lane >> 3) & 1) * 8;
    const uint32_t a_cbit = (uint32_t)(lane >> 4);
    const uint32_t ax = (uint32_t)((a_row >> 1) & 3);
    const int b_row = wn + (lane & 7) + (lane >> 4) * 8;
    const uint32_t b_cbit = (uint32_t)((lane >> 3) & 1);
    const uint32_t bx = (uint32_t)((b_row >> 1) & 3);

    auto issue = [&](int c) {
        const int kc = c * KC;
        const __nv_bfloat16 *Ah, *Al;
        int kA, as_;
        if (kind == 0) {
            Ah = g_zh[parity] + (size_t)row0 * ZD; Al = g_zl[parity] + (size_t)row0 * ZD;
            kA = kc; as_ = ZD;
        } else if (kc < HD) {
            Ah = g_ah + (size_t)row0 * HD; Al = g_al + (size_t)row0 * HD;
            kA = kc; as_ = HD;
        } else {
            Ah = g_hh[parity] + (size_t)row0 * HD; Al = g_hl[parity] + (size_t)row0 * HD;
            kA = kc - HD; as_ = HD;
        }
        const uint32_t stg = sb + (uint32_t)(c % 3) * STAGE_B;
#pragma unroll
        for (int i = 0; i < NVEC; i++) {
            int g = i * 128 + tid;
            uint32_t dst;
            const __nv_bfloat16* srcp;
            if (g < NA) {
                uint32_t row = g >> 2, c4 = g & 3;
                dst = stg + OFF_AH + swz(row, c4);
                srcp = Ah + (size_t)row * as_ + kA + c4 * 8;
            } else if (g < 2 * NA) {
                int j = g - NA; uint32_t row = j >> 2, c4 = j & 3;
                dst = stg + OFF_AL + swz(row, c4);
                srcp = Al + (size_t)row * as_ + kA + c4 * 8;
            } else if (g < 2 * NA + 512) {
                int j = g - 2 * NA; uint32_t row = j >> 2, c4 = j & 3;
                dst = stg + OFF_BH + swz(row, c4);
                srcp = Bh + (size_t)row * bs + kc + c4 * 8;
            } else {
                int j = g - 2 * NA - 512; uint32_t row = j >> 2, c4 = j & 3;
                dst = stg + OFF_BL + swz(row, c4);
                srcp = Bl + (size_t)row * bs + kc + c4 * 8;
            }
            CP_ASYNC16(dst, srcp);
        }
        CP_COMMIT();
    };

    // 3-stage pipeline, single barrier per chunk.
    issue(0);
    issue(1);
    for (int c = 0; c < NCH; c++) {
        if (c + 1 < NCH) {
            asm volatile("cp.async.wait_group 1;" ::: "memory");
        } else {
            asm volatile("cp.async.wait_group 0;" ::: "memory");
        }
        __syncthreads();
        if (c + 2 < NCH) issue(c + 2);

        const uint32_t stg = sb + (uint32_t)(c % 3) * STAGE_B;
#pragma unroll
        for (int kk = 0; kk < 2; kk++) {
            uint32_t Ahf[MF][4], Alf[MF][4], Bhf[8][2], Blf[8][2];
            const uint32_t ac = (uint32_t)(kk * 2) + a_cbit;
            const uint32_t bc = (uint32_t)(kk * 2) + b_cbit;
#pragma unroll
            for (int mf = 0; mf < MF; mf++) {
                uint32_t ad = stg + OFF_AH + (uint32_t)(a_row + mf * 16) * 64u + ((ac ^ ax) << 4);
                LDSM_X4(Ahf[mf][0], Ahf[mf][1], Ahf[mf][2], Ahf[mf][3], ad);
                LDSM_X4(Alf[mf][0], Alf[mf][1], Alf[mf][2], Alf[mf][3], ad + A_TILE_B);
            }
#pragma unroll
            for (int nb = 0; nb < 4; nb++) {
                uint32_t bd = stg + OFF_BH + (uint32_t)(b_row + nb * 16) * 64u + ((bc ^ bx) << 4);
                LDSM_X4(Bhf[nb * 2][0], Bhf[nb * 2][1], Bhf[nb * 2 + 1][0], Bhf[nb * 2 + 1][1], bd);
                LDSM_X4(Blf[nb * 2][0], Blf[nb * 2][1], Blf[nb * 2 + 1][0], Blf[nb * 2 + 1][1], bd + B_TILE_B);
            }
#pragma unroll
            for (int mf = 0; mf < MF; mf++)
#pragma unroll
                for (int nf = 0; nf < 8; nf++) MMA_BF16(acc[mf][nf], Ahf[mf], Bhf[nf]);
#pragma unroll
            for (int mf = 0; mf < MF; mf++)
#pragma unroll
                for (int nf = 0; nf < 8; nf++) MMA_BF16(acc[mf][nf], Ahf[mf], Blf[nf]);
#pragma unroll
            for (int mf = 0; mf < MF; mf++)
#pragma unroll
                for (int nf = 0; nf < 8; nf++) MMA_BF16(acc[mf][nf], Alf[mf], Bhf[nf]);
        }
    }

    // ---------------- epilogue ----------------
    const int quad = lane >> 2, tq = (lane & 3) * 2;
#pragma unroll
    for (int mf = 0; mf < MF; mf++) {
        const int rb = row0 + wm + mf * 16 + quad;
#pragma unroll
        for (int nf = 0; nf < 8; nf++) {
            const int n = n0 + wn + nf * 8 + tq;
#pragma unroll
            for (int half = 0; half < 2; half++) {
                const int m = rb + half * 8;
                const float c0 = acc[mf][nf][half * 2 + 0];
                const float c1 = acc[mf][nf][half * 2 + 1];
                if (kind == 0) {
                    float v0 = lrelu(c0 + b1[n]);
                    float v1 = lrelu(c1 + b1[n + 1]);
                    float h0 = __bfloat162float(__float2bfloat16(v0));
                    float h1 = __bfloat162float(__float2bfloat16(v1));
                    *(uint32_t*)(g_ah + (size_t)m * HD + n) = pack_bf2(h0, h1);
                    *(uint32_t*)(g_al + (size_t)m * HD + n) = pack_bf2(v0 - h0, v1 - h1);
                } else if (is_z) {
                    float2 zv = *(const float2*)(g_z[parity] + (size_t)m * ZD + n);
                    float2 ov = *(const float2*)(z0 + (size_t)m * ZD + n);
                    float v0 = lrelu(c0 + b2[n]) * r + zv.x;
                    float v1 = lrelu(c1 + b2[n + 1]) * r + zv.y;
                    *(float2*)(g_z[parity ^ 1] + (size_t)m * ZD + n) = make_float2(v0, v1);
                    *(float2*)(out + ((size_t)m * T + t) * ZD + n) = make_float2(v0 - ov.x, v1 - ov.y);
                    float h0 = __bfloat162float(__float2bfloat16(v0));
                    float h1 = __bfloat162float(__float2bfloat16(v1));
                    *(uint32_t*)(g_zh[parity ^ 1] + (size_t)m * ZD + n) = pack_bf2(h0, h1);
                    *(uint32_t*)(g_zl[parity ^ 1] + (size_t)m * ZD + n) = pack_bf2(v0 - h0, v1 - h1);
                } else {
                    const int nh = n - ZD;
                    float2 hv = *(const float2*)(g_h[parity] + (size_t)m * HD + nh);
                    float v0 = lrelu(c0 + b3[nh]) * r + hv.x;
                    float v1 = lrelu(c1 + b3[nh + 1]) * r + hv.y;
                    *(float2*)(g_h[parity ^ 1] + (size_t)m * HD + nh) = make_float2(v0, v1);
                    float h0 = __bfloat162float(__float2bfloat16(v0));
                    float h1 = __bfloat162float(__float2bfloat16(v1));
                    *(uint32_t*)(g_hh[parity ^ 1] + (size_t)m * HD + nh) = pack_bf2(h0, h1);
                    *(uint32_t*)(g_hl[parity ^ 1] + (size_t)m * HD + nh) = pack_bf2(v0 - h0, v1 - h1);
                }
            }
        }
    }
}

// ---------------- host ----------------
extern "C" void kernel_launch(void* const* d_in, const int* in_sizes, int n_in,
                              void* d_out, int out_size)
{
    const float* z  = (const float*)d_in[0];
    const float* h0 = (const float*)d_in[1];
    const float* W1 = (const float*)d_in[2];
    const float* b1 = (const float*)d_in[3];
    const float* W2 = (const float*)d_in[4];
    const float* b2 = (const float*)d_in[5];
    const float* W3 = (const float*)d_in[6];
    const float* b3 = (const float*)d_in[7];
    float* out = (float*)d_out;

    const int T = out_size / (BQ * ZD);
    const float r = 0.2f * 4.0f / (float)T;

    const int SM128 = 3 * (2 * 128 * 64 + 2 * 128 * 64);  // 98304
    const int SM32  = 3 * (2 * 32 * 64 + 2 * 128 * 64);   // 61440
    cudaFuncSetAttribute(rec_gemm<128>, cudaFuncAttributeMaxDynamicSharedMemorySize, SM128);
    cudaFuncSetAttribute(rec_gemm<32>, cudaFuncAttributeMaxDynamicSharedMemorySize, SM32);

    const int wtot = HD * ZD + ZD * KD2 + HD * KD2;
    prep_weights<<<(wtot + 255) / 256, 256>>>(W1, W2, W3);
    init_kernel<<<(BQ * ZD + 255) / 256, 256>>>(z, h0, out, T);

    int parity = 0;
    for (int t = 1; t < T; t++) {
        rec_gemm<32><<<dim3(HD / 128, BQ / 32), 128, SM32>>>(0, parity, t, r, b1, b2, b3, z, out, T);
        rec_gemm<128><<<dim3((ZD + HD) / 128, BQ / 128), 128, SM128>>>(1, parity, t, r, b1, b2, b3, z, out, T);
        parity ^= 1;
    }
}

// round 9
// speedup vs baseline: 1.6198x; 1.6198x over previous
#include <cuda_runtime.h>
#include <cuda_fp16.h>
#include <cstdint>

#define BQ 4096
#define ZD 512
#define HD 384
#define KD2 768
#define KC 32

// ---------------- device state ----------------
__device__ float g_z[2][(size_t)BQ * ZD];
__device__ float g_h[2][(size_t)BQ * HD];
// fp16 split activations (hi/lo), ping-pong where stateful
__device__ __half g_zh[2][(size_t)BQ * ZD];
__device__ __half g_zl[2][(size_t)BQ * ZD];
__device__ __half g_hh[2][(size_t)BQ * HD];
__device__ __half g_hl[2][(size_t)BQ * HD];
__device__ __half g_ah[(size_t)BQ * HD];
__device__ __half g_al[(size_t)BQ * HD];
// fp16 weights (single precision term; converted once per launch)
__device__ __half g_w1[(size_t)HD * ZD];
__device__ __half g_w2[(size_t)ZD * KD2];
__device__ __half g_w3[(size_t)HD * KD2];

// ---------------- helpers ----------------
__device__ __forceinline__ uint32_t smem_to_u32(const void* p) {
    uint32_t a;
    asm("{ .reg .u64 t; cvta.to.shared.u64 t, %1; cvt.u32.u64 %0, t; }" : "=r"(a) : "l"(p));
    return a;
}
__device__ __forceinline__ float lrelu(float x) { return x > 0.f ? x : 0.01f * x; }
__device__ __forceinline__ uint32_t pack_h2(float a, float b) {
    __half2 p = __floats2half2_rn(a, b);   // a -> low half (element n)
    return *(uint32_t*)&p;
}
__device__ __forceinline__ void split_h(float v, __half& h, __half& l) {
    h = __float2half_rn(v);
    l = __float2half_rn(v - __half2float(h));
}
__device__ __forceinline__ uint32_t swz(uint32_t row, uint32_t c) {
    return row * 64u + ((c ^ ((row >> 1) & 3u)) << 4);
}

#define CP_ASYNC16(dst, src) \
    asm volatile("cp.async.cg.shared.global [%0], [%1], 16;" \
                 :: "r"(dst), "l"((unsigned long long)__cvta_generic_to_global(src)) : "memory")
#define CP_COMMIT() asm volatile("cp.async.commit_group;" ::: "memory")

#define LDSM_X4(r0, r1, r2, r3, addr) \
    asm volatile("ldmatrix.sync.aligned.m8n8.x4.shared.b16 {%0,%1,%2,%3}, [%4];" \
                 : "=r"(r0), "=r"(r1), "=r"(r2), "=r"(r3) : "r"(addr))

#define MMA_F16(c, a, b) \
    asm volatile("mma.sync.aligned.m16n8k16.row.col.f32.f16.f16.f32 " \
                 "{%0,%1,%2,%3}, {%4,%5,%6,%7}, {%8,%9}, {%0,%1,%2,%3};" \
                 : "+f"((c)[0]), "+f"((c)[1]), "+f"((c)[2]), "+f"((c)[3]) \
                 : "r"((a)[0]), "r"((a)[1]), "r"((a)[2]), "r"((a)[3]), \
                   "r"((b)[0]), "r"((b)[1]))

// ---------------- prep / init ----------------
__global__ void prep_weights(const float* __restrict__ W1, const float* __restrict__ W2,
                             const float* __restrict__ W3)
{
    int i = blockIdx.x * 256 + threadIdx.x;
    const int s1 = HD * ZD, s2 = ZD * KD2, s3 = HD * KD2;
    if (i < s1) g_w1[i] = __float2half_rn(W1[i]);
    else if (i < s1 + s2) { int j = i - s1; g_w2[j] = __float2half_rn(W2[j]); }
    else if (i < s1 + s2 + s3) { int j = i - s1 - s2; g_w3[j] = __float2half_rn(W3[j]); }
}

__global__ void init_kernel(const float* __restrict__ z, const float* __restrict__ hin,
                            float* __restrict__ out, int T)
{
    int idx = blockIdx.x * blockDim.x + threadIdx.x;
    if (idx < BQ * ZD) {
        float v = z[idx];
        g_z[0][idx] = v;
        __half h, l; split_h(v, h, l);
        g_zh[0][idx] = h; g_zl[0][idx] = l;
        int m = idx >> 9, n = idx & (ZD - 1);
        out[((size_t)m * T) * ZD + n] = 0.f;
    }
    if (idx < BQ * HD) {
        float v = hin[idx];
        g_h[0][idx] = v;
        __half h, l; split_h(v, h, l);
        g_hh[0][idx] = h; g_hl[0][idx] = l;
    }
}

// ---------------- tensor-core GEMM (mma.sync fp16, 2-term A-split) ----------------
// Tile TM(M) x 128(N), 128 threads (4 warps 2x2), warp tile (TM/2)x64,
// XOR-swizzled smem (64B rows), 3-stage cp.async pipeline, ONE barrier per chunk,
// 4 CTAs/SM.
template <int TM>
__global__ __launch_bounds__(128, 4)
void rec_gemm(int kind, int parity, int t, float r,
              const float* __restrict__ b1, const float* __restrict__ b2,
              const float* __restrict__ b3, const float* __restrict__ z0,
              float* __restrict__ out, int T)
{
    constexpr int MF = TM / 32;                 // m16 frags per warp
    constexpr int A_TILE_B = TM * 64;
    constexpr int B_TILE_B = 128 * 64;          // 8192
    constexpr int OFF_AH = 0;
    constexpr int OFF_AL = A_TILE_B;
    constexpr int OFF_B  = 2 * A_TILE_B;
    constexpr int STAGE_B = 2 * A_TILE_B + B_TILE_B;
    constexpr int NA = TM * 4;                  // 16B chunks per A tile
    constexpr int NVEC = (2 * NA + 512) / 128;

    extern __shared__ char smem[];
    const uint32_t sb = smem_to_u32(smem);
    const int tid = threadIdx.x;
    const int wid = tid >> 5, lane = tid & 31;
    const int wm = (wid >> 1) * (TM / 2);
    const int wn = (wid & 1) * 64;
    const int n0 = blockIdx.x * 128;
    const int row0 = blockIdx.y * TM;
    const bool is_z = (n0 < ZD);
    const int NCH = kind ? (KD2 / KC) : (ZD / KC);

    const __half* B;
    int bs;
    if (kind == 0)  { B = g_w1 + (size_t)n0 * ZD;         bs = ZD; }
    else if (is_z)  { B = g_w2 + (size_t)n0 * KD2;        bs = KD2; }
    else            { B = g_w3 + (size_t)(n0 - ZD) * KD2; bs = KD2; }

    float acc[MF][8][4];
#pragma unroll
    for (int i = 0; i < MF; i++)
#pragma unroll
        for (int j = 0; j < 8; j++)
#pragma unroll
            for (int k = 0; k < 4; k++) acc[i][j][k] = 0.f;

    const int a_row = wm + (lane & 7) + ((lane >> 3) & 1) * 8;
    const uint32_t a_cbit = (uint32_t)(lane >> 4);
    const uint32_t ax = (uint32_t)((a_row >> 1) & 3);
    const int b_row = wn + (lane & 7) + (lane >> 4) * 8;
    const uint32_t b_cbit = (uint32_t)((lane >> 3) & 1);
    const uint32_t bx = (uint32_t)((b_row >> 1) & 3);

    auto issue = [&](int c) {
        const int kc = c * KC;
        const __half *Ah, *Al;
        int kA, as_;
        if (kind == 0) {
            Ah = g_zh[parity] + (size_t)row0 * ZD; Al = g_zl[parity] + (size_t)row0 * ZD;
            kA = kc; as_ = ZD;
        } else if (kc < HD) {
            Ah = g_ah + (size_t)row0 * HD; Al = g_al + (size_t)row0 * HD;
            kA = kc; as_ = HD;
        } else {
            Ah = g_hh[parity] + (size_t)row0 * HD; Al = g_hl[parity] + (size_t)row0 * HD;
            kA = kc - HD; as_ = HD;
        }
        const uint32_t stg = sb + (uint32_t)(c % 3) * STAGE_B;
#pragma unroll
        for (int i = 0; i < NVEC; i++) {
            int g = i * 128 + tid;
            uint32_t dst;
            const __half* srcp;
            if (g < NA) {
                uint32_t row = g >> 2, c4 = g & 3;
                dst = stg + OFF_AH + swz(row, c4);
                srcp = Ah + (size_t)row * as_ + kA + c4 * 8;
            } else if (g < 2 * NA) {
                int j = g - NA; uint32_t row = j >> 2, c4 = j & 3;
                dst = stg + OFF_AL + swz(row, c4);
                srcp = Al + (size_t)row * as_ + kA + c4 * 8;
            } else {
                int j = g - 2 * NA; uint32_t row = j >> 2, c4 = j & 3;
                dst = stg + OFF_B + swz(row, c4);
                srcp = B + (size_t)row * bs + kc + c4 * 8;
            }
            CP_ASYNC16(dst, srcp);
        }
        CP_COMMIT();
    };

    // 3-stage pipeline, single barrier per chunk.
    issue(0);
    issue(1);
    for (int c = 0; c < NCH; c++) {
        if (c + 1 < NCH) {
            asm volatile("cp.async.wait_group 1;" ::: "memory");
        } else {
            asm volatile("cp.async.wait_group 0;" ::: "memory");
        }
        __syncthreads();
        if (c + 2 < NCH) issue(c + 2);

        const uint32_t stg = sb + (uint32_t)(c % 3) * STAGE_B;
#pragma unroll
        for (int kk = 0; kk < 2; kk++) {
            uint32_t Ahf[MF][4], Alf[MF][4], Bf[8][2];
            const uint32_t ac = (uint32_t)(kk * 2) + a_cbit;
            const uint32_t bc = (uint32_t)(kk * 2) + b_cbit;
#pragma unroll
            for (int mf = 0; mf < MF; mf++) {
                uint32_t ad = stg + OFF_AH + (uint32_t)(a_row + mf * 16) * 64u + ((ac ^ ax) << 4);
                LDSM_X4(Ahf[mf][0], Ahf[mf][1], Ahf[mf][2], Ahf[mf][3], ad);
                LDSM_X4(Alf[mf][0], Alf[mf][1], Alf[mf][2], Alf[mf][3], ad + A_TILE_B);
            }
#pragma unroll
            for (int nb = 0; nb < 4; nb++) {
                uint32_t bd = stg + OFF_B + (uint32_t)(b_row + nb * 16) * 64u + ((bc ^ bx) << 4);
                LDSM_X4(Bf[nb * 2][0], Bf[nb * 2][1], Bf[nb * 2 + 1][0], Bf[nb * 2 + 1][1], bd);
            }
#pragma unroll
            for (int mf = 0; mf < MF; mf++)
#pragma unroll
                for (int nf = 0; nf < 8; nf++) MMA_F16(acc[mf][nf], Ahf[mf], Bf[nf]);
#pragma unroll
            for (int mf = 0; mf < MF; mf++)
#pragma unroll
                for (int nf = 0; nf < 8; nf++) MMA_F16(acc[mf][nf], Alf[mf], Bf[nf]);
        }
    }

    // ---------------- epilogue ----------------
    const int quad = lane >> 2, tq = (lane & 3) * 2;
#pragma unroll
    for (int mf = 0; mf < MF; mf++) {
        const int rb = row0 + wm + mf * 16 + quad;
#pragma unroll
        for (int nf = 0; nf < 8; nf++) {
            const int n = n0 + wn + nf * 8 + tq;
#pragma unroll
            for (int half = 0; half < 2; half++) {
                const int m = rb + half * 8;
                const float c0 = acc[mf][nf][half * 2 + 0];
                const float c1 = acc[mf][nf][half * 2 + 1];
                if (kind == 0) {
                    float v0 = lrelu(c0 + b1[n]);
                    float v1 = lrelu(c1 + b1[n + 1]);
                    float h0 = __half2float(__float2half_rn(v0));
                    float h1 = __half2float(__float2half_rn(v1));
                    *(uint32_t*)(g_ah + (size_t)m * HD + n) = pack_h2(h0, h1);
                    *(uint32_t*)(g_al + (size_t)m * HD + n) = pack_h2(v0 - h0, v1 - h1);
                } else if (is_z) {
                    float2 zv = *(const float2*)(g_z[parity] + (size_t)m * ZD + n);
                    float2 ov = *(const float2*)(z0 + (size_t)m * ZD + n);
                    float v0 = lrelu(c0 + b2[n]) * r + zv.x;
                    float v1 = lrelu(c1 + b2[n + 1]) * r + zv.y;
                    *(float2*)(g_z[parity ^ 1] + (size_t)m * ZD + n) = make_float2(v0, v1);
                    *(float2*)(out + ((size_t)m * T + t) * ZD + n) = make_float2(v0 - ov.x, v1 - ov.y);
                    float h0 = __half2float(__float2half_rn(v0));
                    float h1 = __half2float(__float2half_rn(v1));
                    *(uint32_t*)(g_zh[parity ^ 1] + (size_t)m * ZD + n) = pack_h2(h0, h1);
                    *(uint32_t*)(g_zl[parity ^ 1] + (size_t)m * ZD + n) = pack_h2(v0 - h0, v1 - h1);
                } else {
                    const int nh = n - ZD;
                    float2 hv = *(const float2*)(g_h[parity] + (size_t)m * HD + nh);
                    float v0 = lrelu(c0 + b3[nh]) * r + hv.x;
                    float v1 = lrelu(c1 + b3[nh + 1]) * r + hv.y;
                    *(float2*)(g_h[parity ^ 1] + (size_t)m * HD + nh) = make_float2(v0, v1);
                    float h0 = __half2float(__float2half_rn(v0));
                    float h1 = __half2float(__float2half_rn(v1));
                    *(uint32_t*)(g_hh[parity ^ 1] + (size_t)m * HD + nh) = pack_h2(h0, h1);
                    *(uint32_t*)(g_hl[parity ^ 1] + (size_t)m * HD + nh) = pack_h2(v0 - h0, v1 - h1);
                }
            }
        }
    }
}

// ---------------- host ----------------
extern "C" void kernel_launch(void* const* d_in, const int* in_sizes, int n_in,
                              void* d_out, int out_size)
{
    const float* z  = (const float*)d_in[0];
    const float* h0 = (const float*)d_in[1];
    const float* W1 = (const float*)d_in[2];
    const float* b1 = (const float*)d_in[3];
    const float* W2 = (const float*)d_in[4];
    const float* b2 = (const float*)d_in[5];
    const float* W3 = (const float*)d_in[6];
    const float* b3 = (const float*)d_in[7];
    float* out = (float*)d_out;

    const int T = out_size / (BQ * ZD);
    const float r = 0.2f * 4.0f / (float)T;

    const int SM64 = 3 * (2 * 64 * 64 + 128 * 64);   // 49152
    const int SM32 = 3 * (2 * 32 * 64 + 128 * 64);   // 36864
    cudaFuncSetAttribute(rec_gemm<64>, cudaFuncAttributeMaxDynamicSharedMemorySize, SM64);
    cudaFuncSetAttribute(rec_gemm<32>, cudaFuncAttributeMaxDynamicSharedMemorySize, SM32);

    const int wtot = HD * ZD + ZD * KD2 + HD * KD2;
    prep_weights<<<(wtot + 255) / 256, 256>>>(W1, W2, W3);
    init_kernel<<<(BQ * ZD + 255) / 256, 256>>>(z, h0, out, T);

    int parity = 0;
    for (int t = 1; t < T; t++) {
        rec_gemm<32><<<dim3(HD / 128, BQ / 32), 128, SM32>>>(0, parity, t, r, b1, b2, b3, z, out, T);
        rec_gemm<64><<<dim3((ZD + HD) / 128, BQ / 64), 128, SM64>>>(1, parity, t, r, b1, b2, b3, z, out, T);
        parity ^= 1;
    }
}

// round 10
// speedup vs baseline: 2.5552x; 1.5775x over previous
#include <cuda_runtime.h>
#include <cuda_fp16.h>
#include <cstdint>

#define BQ 4096
#define ZD 512
#define HD 384
#define KD2 768
#define KC 64

// ---------------- device state ----------------
__device__ float g_z[2][(size_t)BQ * ZD];
__device__ float g_h[2][(size_t)BQ * HD];
// fp16 activations (single precision term), ping-pong where stateful
__device__ __half g_zh[2][(size_t)BQ * ZD];
__device__ __half g_hh[2][(size_t)BQ * HD];
__device__ __half g_ah[(size_t)BQ * HD];
// fp16 weights (converted once per launch)
__device__ __half g_w1[(size_t)HD * ZD];
__device__ __half g_w2[(size_t)ZD * KD2];
__device__ __half g_w3[(size_t)HD * KD2];

// ---------------- helpers ----------------
__device__ __forceinline__ uint32_t smem_to_u32(const void* p) {
    uint32_t a;
    asm("{ .reg .u64 t; cvta.to.shared.u64 t, %1; cvt.u32.u64 %0, t; }" : "=r"(a) : "l"(p));
    return a;
}
__device__ __forceinline__ float lrelu(float x) { return x > 0.f ? x : 0.01f * x; }
__device__ __forceinline__ uint32_t pack_h2(float a, float b) {
    __half2 p = __floats2half2_rn(a, b);   // a -> low half (element n)
    return *(uint32_t*)&p;
}
// 128B-row swizzle: 16B chunk c (0..7) XOR low 3 row bits
__device__ __forceinline__ uint32_t swz128(uint32_t row, uint32_t c) {
    return row * 128u + ((c ^ (row & 7u)) << 4);
}

#define CP_ASYNC16(dst, src) \
    asm volatile("cp.async.cg.shared.global [%0], [%1], 16;" \
                 :: "r"(dst), "l"((unsigned long long)__cvta_generic_to_global(src)) : "memory")
#define CP_COMMIT() asm volatile("cp.async.commit_group;" ::: "memory")

#define LDSM_X4(r0, r1, r2, r3, addr) \
    asm volatile("ldmatrix.sync.aligned.m8n8.x4.shared.b16 {%0,%1,%2,%3}, [%4];" \
                 : "=r"(r0), "=r"(r1), "=r"(r2), "=r"(r3) : "r"(addr))

#define MMA_F16(c, a, b) \
    asm volatile("mma.sync.aligned.m16n8k16.row.col.f32.f16.f16.f32 " \
                 "{%0,%1,%2,%3}, {%4,%5,%6,%7}, {%8,%9}, {%0,%1,%2,%3};" \
                 : "+f"((c)[0]), "+f"((c)[1]), "+f"((c)[2]), "+f"((c)[3]) \
                 : "r"((a)[0]), "r"((a)[1]), "r"((a)[2]), "r"((a)[3]), \
                   "r"((b)[0]), "r"((b)[1]))

// ---------------- prep / init ----------------
__global__ void prep_weights(const float* __restrict__ W1, const float* __restrict__ W2,
                             const float* __restrict__ W3)
{
    int i = blockIdx.x * 256 + threadIdx.x;
    const int s1 = HD * ZD, s2 = ZD * KD2, s3 = HD * KD2;
    if (i < s1) g_w1[i] = __float2half_rn(W1[i]);
    else if (i < s1 + s2) { int j = i - s1; g_w2[j] = __float2half_rn(W2[j]); }
    else if (i < s1 + s2 + s3) { int j = i - s1 - s2; g_w3[j] = __float2half_rn(W3[j]); }
}

__global__ void init_kernel(const float* __restrict__ z, const float* __restrict__ hin,
                            float* __restrict__ out, int T)
{
    int idx = blockIdx.x * blockDim.x + threadIdx.x;
    if (idx < BQ * ZD) {
        float v = z[idx];
        g_z[0][idx] = v;
        g_zh[0][idx] = __float2half_rn(v);
        int m = idx >> 9, n = idx & (ZD - 1);
        out[((size_t)m * T) * ZD + n] = 0.f;
    }
    if (idx < BQ * HD) {
        float v = hin[idx];
        g_h[0][idx] = v;
        g_hh[0][idx] = __float2half_rn(v);
    }
}

// ---------------- tensor-core GEMM (mma.sync fp16, single term) ----------------
// Tile TM(M) x 128(N), 128 threads (4 warps 2x2), warp tile (TM/2)x64,
// KC=64 chunks (128B rows, XOR swizzle), 2-stage cp.async double buffer,
// ONE barrier per chunk, 4 CTAs/SM.
template <int TM>
__global__ __launch_bounds__(128, 4)
void rec_gemm(int kind, int parity, int t, float r,
              const float* __restrict__ b1, const float* __restrict__ b2,
              const float* __restrict__ b3, const float* __restrict__ z0,
              float* __restrict__ out, int T)
{
    constexpr int MF = TM / 32;                 // m16 frags per warp
    constexpr int A_TILE_B = TM * 128;          // TM rows x 128 B
    constexpr int B_TILE_B = 128 * 128;         // 16384
    constexpr int OFF_A = 0;
    constexpr int OFF_B = A_TILE_B;
    constexpr int STAGE_B = A_TILE_B + B_TILE_B;
    constexpr int NA = TM * 8;                  // 16B chunks in A tile
    constexpr int NVEC = (NA + 1024) / 128;     // chunks per thread

    extern __shared__ char smem[];
    const uint32_t sb = smem_to_u32(smem);
    const int tid = threadIdx.x;
    const int wid = tid >> 5, lane = tid & 31;
    const int wm = (wid >> 1) * (TM / 2);
    const int wn = (wid & 1) * 64;
    const int n0 = blockIdx.x * 128;
    const int row0 = blockIdx.y * TM;
    const bool is_z = (n0 < ZD);
    const int NCH = kind ? (KD2 / KC) : (ZD / KC);

    const __half* B;
    int bs;
    if (kind == 0)  { B = g_w1 + (size_t)n0 * ZD;         bs = ZD; }
    else if (is_z)  { B = g_w2 + (size_t)n0 * KD2;        bs = KD2; }
    else            { B = g_w3 + (size_t)(n0 - ZD) * KD2; bs = KD2; }

    float acc[MF][8][4];
#pragma unroll
    for (int i = 0; i < MF; i++)
#pragma unroll
        for (int j = 0; j < 8; j++)
#pragma unroll
            for (int k = 0; k < 4; k++) acc[i][j][k] = 0.f;

    const int a_row = wm + (lane & 7) + ((lane >> 3) & 1) * 8;
    const uint32_t a_cbit = (uint32_t)(lane >> 4);          // 16B half of k16
    const int b_row = wn + (lane & 7) + (lane >> 4) * 8;
    const uint32_t b_cbit = (uint32_t)((lane >> 3) & 1);
    const uint32_t lx = (uint32_t)(lane & 7);               // row&7 for both A and B

    auto issue = [&](int c) {
        const int kc = c * KC;
        const __half* A;
        int kA, as_;
        if (kind == 0) {
            A = g_zh[parity] + (size_t)row0 * ZD;
            kA = kc; as_ = ZD;
        } else if (kc < HD) {
            A = g_ah + (size_t)row0 * HD;
            kA = kc; as_ = HD;
        } else {
            A = g_hh[parity] + (size_t)row0 * HD;
            kA = kc - HD; as_ = HD;
        }
        const uint32_t stg = sb + (uint32_t)(c & 1) * STAGE_B;
#pragma unroll
        for (int i = 0; i < NVEC; i++) {
            int g = i * 128 + tid;
            uint32_t dst;
            const __half* srcp;
            if (g < NA) {
                uint32_t row = g >> 3, c8 = g & 7;
                dst = stg + OFF_A + swz128(row, c8);
                srcp = A + (size_t)row * as_ + kA + c8 * 8;
            } else {
                int j = g - NA;
                uint32_t row = j >> 3, c8 = j & 7;
                dst = stg + OFF_B + swz128(row, c8);
                srcp = B + (size_t)row * bs + kc + c8 * 8;
            }
            CP_ASYNC16(dst, srcp);
        }
        CP_COMMIT();
    };

    // 2-stage double buffer, single barrier per chunk.
    issue(0);
    for (int c = 0; c < NCH; c++) {
        asm volatile("cp.async.wait_group 0;" ::: "memory");   // chunk c data ready
        __syncthreads();                                        // stage (c+1)&1 free
        if (c + 1 < NCH) issue(c + 1);                          // overlap with compute

        const uint32_t stg = sb + (uint32_t)(c & 1) * STAGE_B;
#pragma unroll
        for (int kk = 0; kk < 4; kk++) {
            uint32_t Af[MF][4], Bf[8][2];
            const uint32_t ac = (uint32_t)(kk * 2) + a_cbit;
            const uint32_t bc = (uint32_t)(kk * 2) + b_cbit;
#pragma unroll
            for (int mf = 0; mf < MF; mf++) {
                uint32_t ad = stg + OFF_A + (uint32_t)(a_row + mf * 16) * 128u + ((ac ^ lx) << 4);
                LDSM_X4(Af[mf][0], Af[mf][1], Af[mf][2], Af[mf][3], ad);
            }
#pragma unroll
            for (int nb = 0; nb < 4; nb++) {
                uint32_t bd = stg + OFF_B + (uint32_t)(b_row + nb * 16) * 128u + ((bc ^ lx) << 4);
                LDSM_X4(Bf[nb * 2][0], Bf[nb * 2][1], Bf[nb * 2 + 1][0], Bf[nb * 2 + 1][1], bd);
            }
#pragma unroll
            for (int mf = 0; mf < MF; mf++)
#pragma unroll
                for (int nf = 0; nf < 8; nf++) MMA_F16(acc[mf][nf], Af[mf], Bf[nf]);
        }
    }

    // ---------------- epilogue ----------------
    const int quad = lane >> 2, tq = (lane & 3) * 2;
#pragma unroll
    for (int mf = 0; mf < MF; mf++) {
        const int rb = row0 + wm + mf * 16 + quad;
#pragma unroll
        for (int nf = 0; nf < 8; nf++) {
            const int n = n0 + wn + nf * 8 + tq;
#pragma unroll
            for (int half = 0; half < 2; half++) {
                const int m = rb + half * 8;
                const float c0 = acc[mf][nf][half * 2 + 0];
                const float c1 = acc[mf][nf][half * 2 + 1];
                if (kind == 0) {
                    float v0 = lrelu(c0 + b1[n]);
                    float v1 = lrelu(c1 + b1[n + 1]);
                    *(uint32_t*)(g_ah + (size_t)m * HD + n) = pack_h2(v0, v1);
                } else if (is_z) {
                    float2 zv = *(const float2*)(g_z[parity] + (size_t)m * ZD + n);
                    float2 ov = *(const float2*)(z0 + (size_t)m * ZD + n);
                    float v0 = lrelu(c0 + b2[n]) * r + zv.x;
                    float v1 = lrelu(c1 + b2[n + 1]) * r + zv.y;
                    *(float2*)(g_z[parity ^ 1] + (size_t)m * ZD + n) = make_float2(v0, v1);
                    *(float2*)(out + ((size_t)m * T + t) * ZD + n) = make_float2(v0 - ov.x, v1 - ov.y);
                    *(uint32_t*)(g_zh[parity ^ 1] + (size_t)m * ZD + n) = pack_h2(v0, v1);
                } else {
                    const int nh = n - ZD;
                    float2 hv = *(const float2*)(g_h[parity] + (size_t)m * HD + nh);
                    float v0 = lrelu(c0 + b3[nh]) * r + hv.x;
                    float v1 = lrelu(c1 + b3[nh + 1]) * r + hv.y;
                    *(float2*)(g_h[parity ^ 1] + (size_t)m * HD + nh) = make_float2(v0, v1);
                    *(uint32_t*)(g_hh[parity ^ 1] + (size_t)m * HD + nh) = pack_h2(v0, v1);
                }
            }
        }
    }
}

// ---------------- host ----------------
extern "C" void kernel_launch(void* const* d_in, const int* in_sizes, int n_in,
                              void* d_out, int out_size)
{
    const float* z  = (const float*)d_in[0];
    const float* h0 = (const float*)d_in[1];
    const float* W1 = (const float*)d_in[2];
    const float* b1 = (const float*)d_in[3];
    const float* W2 = (const float*)d_in[4];
    const float* b2 = (const float*)d_in[5];
    const float* W3 = (const float*)d_in[6];
    const float* b3 = (const float*)d_in[7];
    float* out = (float*)d_out;

    const int T = out_size / (BQ * ZD);
    const float r = 0.2f * 4.0f / (float)T;

    const int SM64 = 2 * (64 * 128 + 128 * 128);   // 49152
    const int SM32 = 2 * (32 * 128 + 128 * 128);   // 40960
    cudaFuncSetAttribute(rec_gemm<64>, cudaFuncAttributeMaxDynamicSharedMemorySize, SM64);
    cudaFuncSetAttribute(rec_gemm<32>, cudaFuncAttributeMaxDynamicSharedMemorySize, SM32);

    const int wtot = HD * ZD + ZD * KD2 + HD * KD2;
    prep_weights<<<(wtot + 255) / 256, 256>>>(W1, W2, W3);
    init_kernel<<<(BQ * ZD + 255) / 256, 256>>>(z, h0, out, T);

    int parity = 0;
    for (int t = 1; t < T; t++) {
        rec_gemm<32><<<dim3(HD / 128, BQ / 32), 128, SM32>>>(0, parity, t, r, b1, b2, b3, z, out, T);
        rec_gemm<64><<<dim3((ZD + HD) / 128, BQ / 64), 128, SM64>>>(1, parity, t, r, b1, b2, b3, z, out, T);
        parity ^= 1;
    }
}